// round 16
// baseline (speedup 1.0000x reference)
#include <cuda_runtime.h>

// sLSTM: B=256, T=512, D=8, H=120, L=4, NH=8, HD=15
// R7 winner + rotated (software-pipelined, depth-1) scan body:
//   per step: [h-LDS + 60 h-FMAs onto precomputed gates g*] -> [cell + STS]
//   -> [compute g* for step t+1 from x: independent, fills the cell-tail /
//   STS-drain / h-LDS latency window].
// g* recomputed at each layer start; chunk-boundary prefetch reads the next
// chunk's x row (untouched by this chunk's projection) so g* carries across
// chunks. 8-ull pad after x2 covers the single out-of-range read at layer
// end (its g* is discarded).
// Structure otherwise identical to R7: 128 CTAs x 128 thr; warp k owns head
// pair (k,k+4) for 2 batches, packed (j,j+60) f32x2 outputs, warp-private
// ring h-exchange, folded log2e/0.5 weights, single-exp cell, chunked
// down-projection.

#define B_ 256
#define T_ 512
#define D_ 8
#define H_ 120
#define L_ 4
#define NPAIR 60
#define ST 61              // hs row stride (ull)
#define BST (64 * ST + 1)  // hs batch stride (ull)
#define XST 4097           // x batch stride (ull)
#define LOG2E 1.4426950408889634f

typedef unsigned long long ull;

__device__ float g_last[B_ * D_];

__device__ __forceinline__ ull f2pack(float x, float y) {
    ull r; asm("mov.b64 %0, {%1, %2};" : "=l"(r) : "f"(x), "f"(y)); return r;
}
__device__ __forceinline__ void f2unpack(ull v, float& x, float& y) {
    asm("mov.b64 {%0, %1}, %2;" : "=f"(x), "=f"(y) : "l"(v));
}
__device__ __forceinline__ float f2lo(ull v) {
    float x, y; f2unpack(v, x, y); return x;
}
__device__ __forceinline__ ull f2fma(ull a, ull b, ull c) {
    ull d; asm("fma.rn.f32x2 %0, %1, %2, %3;" : "=l"(d) : "l"(a), "l"(b), "l"(c));
    return d;
}
__device__ __forceinline__ float tanh_ap(float x) {
    float r; asm("tanh.approx.f32 %0, %1;" : "=f"(r) : "f"(x)); return r;
}
__device__ __forceinline__ float rcp_ap(float x) {
    float r; asm("rcp.approx.f32 %0, %1;" : "=f"(r) : "f"(x)); return r;
}
__device__ __forceinline__ float ex2_ap(float x) {
    float r; asm("ex2.approx.f32 %0, %1;" : "=f"(r) : "f"(x)); return r;
}

// sLSTM cell. it/ft pre-scaled by log2e, ot pre-scaled by 0.5.
// mn=max(it,b): one gate factor is exactly 1, the other 2^(-|it-b|).
__device__ __forceinline__ float cellf(float it, float ft, float zt, float ot,
                                       float& c, float& nn, float& m) {
    float z  = tanh_ap(zt);
    float o  = fmaf(tanh_ap(ot), 0.5f, 0.5f);
    float b  = ft + m;
    float mn = fmaxf(it, b);
    float e  = ex2_ap(-fabsf(it - b));
    bool ag  = (it >= b);
    float ip = ag ? 1.f : e;
    float fp = ag ? e : 1.f;
    c  = fp * c  + ip * z;
    nn = fp * nn + ip;
    m  = mn;
    return o * c * rcp_ap(nn);
}

// shared layout (ull units):
//   x2  [2][XST] + 8 pad   residual/x stream, duplicated (v,v)
//   hsb [2][BST]           h history ring (paired), rows of ST
//   wp2 [8*60]             paired Wp
//   bps [8 floats]
#define SM_X2  0
#define SM_HS  (2 * XST + 8)
#define SM_WP  (SM_HS + 2 * BST)
#define SM_BP  (SM_WP + 480)
#define SM_TOT (SM_BP + 4)
#define SMEM_BYTES (SM_TOT * 8 + 16)

__global__ void __launch_bounds__(128, 1) slstm_kernel(
    const float* __restrict__ X,
    const float* __restrict__ Wi, const float* __restrict__ Wf,
    const float* __restrict__ Wz, const float* __restrict__ Wo,
    const float* __restrict__ Ri, const float* __restrict__ Rf,
    const float* __restrict__ Rz, const float* __restrict__ Ro,
    const float* __restrict__ bi, const float* __restrict__ bf,
    const float* __restrict__ bz, const float* __restrict__ bo,
    const float* __restrict__ Wp, const float* __restrict__ bp)
{
    extern __shared__ ull sm[];
    ull* x2  = sm + SM_X2;
    ull* hsb = sm + SM_HS;
    ull* wp2 = sm + SM_WP;
    float* bps = (float*)(sm + SM_BP);

    const int tid  = threadIdx.x;
    const int lane = tid & 31;
    const int k    = tid >> 5;           // warp id == head block (pairs k+4)
    const int half = (lane >> 4) & 1;    // batch within CTA
    const int e    = lane & 15;
    const bool act = (e < 15);
    const int b0   = blockIdx.x * 2;
    const int ec   = act ? e : 14;
    const int slot = k * 15 + ec;

    // load input x for both batches, duplicated (v,v)
    for (int idx = tid; idx < 2 * T_ * D_; idx += 128) {
        int bbi = idx >> 12;
        int i   = idx & 4095;
        float v = X[(b0 + bbi) * (T_ * D_) + i];
        x2[bbi * XST + i] = f2pack(v, v);
    }

    #pragma unroll 1
    for (int l = 0; l < L_; l++) {
        // ---- packed weights into registers (i/f scaled log2e, o scaled .5) ----
        ull rIv[15], rFv[15], rZv[15], rOv[15];
        ull wIv[8],  wFv[8],  wZv[8],  wOv[8];
        ull bIv, bFv, bZv, bOv;
        {
            const int j0 = slot, j1 = slot + 60;
            const float* wi = Wi + l * H_ * D_;
            const float* wf = Wf + l * H_ * D_;
            const float* wz = Wz + l * H_ * D_;
            const float* wo = Wo + l * H_ * D_;
            #pragma unroll
            for (int d = 0; d < 8; d++) {
                wIv[d] = f2pack(LOG2E * wi[j0 * 8 + d], LOG2E * wi[j1 * 8 + d]);
                wFv[d] = f2pack(LOG2E * wf[j0 * 8 + d], LOG2E * wf[j1 * 8 + d]);
                wZv[d] = f2pack(wz[j0 * 8 + d], wz[j1 * 8 + d]);
                wOv[d] = f2pack(0.5f * wo[j0 * 8 + d], 0.5f * wo[j1 * 8 + d]);
            }
            const float* ri = Ri + l * 8 * 225;
            const float* rf = Rf + l * 8 * 225;
            const float* rz = Rz + l * 8 * 225;
            const float* ro = Ro + l * 8 * 225;
            #pragma unroll
            for (int d = 0; d < 15; d++) {
                int i0 = k * 225 + d * 15 + ec;
                int i1 = (k + 4) * 225 + d * 15 + ec;
                rIv[d] = f2pack(LOG2E * ri[i0], LOG2E * ri[i1]);
                rFv[d] = f2pack(LOG2E * rf[i0], LOG2E * rf[i1]);
                rZv[d] = f2pack(rz[i0], rz[i1]);
                rOv[d] = f2pack(0.5f * ro[i0], 0.5f * ro[i1]);
            }
            bIv = f2pack(LOG2E * bi[l * H_ + j0], LOG2E * bi[l * H_ + j1]);
            bFv = f2pack(LOG2E * bf[l * H_ + j0], LOG2E * bf[l * H_ + j1]);
            bZv = f2pack(bz[l * H_ + j0], bz[l * H_ + j1]);
            bOv = f2pack(0.5f * bo[l * H_ + j0], 0.5f * bo[l * H_ + j1]);
        }
        for (int idx = tid; idx < 8 * NPAIR; idx += 128) {
            int d = idx / NPAIR, p = idx - d * NPAIR;
            const float* wp = Wp + l * D_ * H_;
            wp2[idx] = f2pack(wp[d * H_ + p], wp[d * H_ + p + 60]);
        }
        if (tid < 8) bps[tid] = bp[l * D_ + tid];
        // zero the ring's "step -1" row
        if (act) {
            hsb[0 * BST + 63 * ST + slot] = 0ull;
            hsb[1 * BST + 63 * ST + slot] = 0ull;
        }
        __syncthreads();

        float c0 = 0.f, c1 = 0.f, n0 = 0.f, n1 = 0.f, m0 = 0.f, m1 = 0.f;

        ull* __restrict__ hrow = hsb + half * BST;
        const ull* __restrict__ xbase = x2 + half * XST;
        const int hoff = k * 15;

        // initial gate preactivations for step 0 of this layer
        ull gI = bIv, gF = bFv, gZ = bZv, gO = bOv;
        {
            const ull* __restrict__ xr = xbase;
            #pragma unroll
            for (int d = 0; d < 8; d++) {
                ull xv = xr[d];
                gI = f2fma(xv, wIv[d], gI);
                gF = f2fma(xv, wFv[d], gF);
                gZ = f2fma(xv, wZv[d], gZ);
                gO = f2fma(xv, wOv[d], gO);
            }
        }

        #pragma unroll 1
        for (int ch = 0; ch < 8; ch++) {
            const int tbase = ch * 64;
            // ---- scan 64 steps: rotated body (h-FMAs -> cell -> next-x) ----
            #pragma unroll 2
            for (int tt = 0; tt < 64; tt++) {
                const int p = (tt - 1) & 63;
                ull aI = gI, aF = gF, aZ = gZ, aO = gO;
                const ull* __restrict__ hr = hrow + p * ST + hoff;
                #pragma unroll
                for (int d = 0; d < 15; d++) {
                    ull hv = hr[d];
                    aI = f2fma(hv, rIv[d], aI);
                    aF = f2fma(hv, rFv[d], aF);
                    aZ = f2fma(hv, rZv[d], aZ);
                    aO = f2fma(hv, rOv[d], aO);
                }
                float itx, ity, ftx, fty, ztx, zty, otx, oty;
                f2unpack(aI, itx, ity); f2unpack(aF, ftx, fty);
                f2unpack(aZ, ztx, zty); f2unpack(aO, otx, oty);
                float h0 = cellf(itx, ftx, ztx, otx, c0, n0, m0);
                float h1 = cellf(ity, fty, zty, oty, c1, n1, m1);
                if (act)
                    hrow[tt * ST + slot] = f2pack(h0, h1);
                // prefetch gates for step t+1 from x (independent of h):
                // fills the cell-tail / STS-drain / next-h-LDS window.
                gI = bIv; gF = bFv; gZ = bZv; gO = bOv;
                const ull* __restrict__ xr = xbase + (tbase + tt + 1) * 8;
                #pragma unroll
                for (int d = 0; d < 8; d++) {
                    ull xv = xr[d];
                    gI = f2fma(xv, wIv[d], gI);
                    gF = f2fma(xv, wFv[d], gF);
                    gZ = f2fma(xv, wZv[d], gZ);
                    gO = f2fma(xv, wOv[d], gO);
                }
            }
            __syncthreads();
            // ---- projection: x[t] += hs[t] @ Wp^T + bp (64-step chunk) ----
            {
                const int tl = tid & 63;
                const int bb = tid >> 6;
                ull acc[8];
                #pragma unroll
                for (int d = 0; d < 8; d++) acc[d] = 0ull;
                const ull* __restrict__ hsr = hsb + bb * BST + tl * ST;
                #pragma unroll 4
                for (int pp = 0; pp < NPAIR; pp++) {
                    ull hvv = hsr[pp];
                    #pragma unroll
                    for (int d = 0; d < 8; d++)
                        acc[d] = f2fma(hvv, wp2[d * NPAIR + pp], acc[d]);
                }
                ull* xw = x2 + bb * XST + (tbase + tl) * 8;
                #pragma unroll
                for (int d = 0; d < 8; d++) {
                    float ax, ay; f2unpack(acc[d], ax, ay);
                    float nv = f2lo(xw[d]) + ax + ay + bps[d];
                    xw[d] = f2pack(nv, nv);
                }
            }
            __syncthreads();
        }
    }

    if (tid < 16) {
        int bbi = tid >> 3, d = tid & 7;
        g_last[(b0 + bbi) * D_ + d] = f2lo(x2[bbi * XST + 511 * 8 + d]);
    }
}

__global__ void finalize_kernel(const float* __restrict__ gamma,
                                const float* __restrict__ beta,
                                const float* __restrict__ wfc,
                                const float* __restrict__ bfc,
                                float* __restrict__ out)
{
    __shared__ float red[8][8];
    __shared__ float smu[8], svar[8];
    int b = threadIdx.x;
    int lane = b & 31, w = b >> 5;
    float v[8];
    #pragma unroll
    for (int d = 0; d < 8; d++) v[d] = g_last[b * 8 + d];

    #pragma unroll
    for (int d = 0; d < 8; d++) {
        float sv = v[d];
        #pragma unroll
        for (int o = 16; o > 0; o >>= 1) sv += __shfl_xor_sync(0xffffffffu, sv, o);
        if (lane == 0) red[d][w] = sv;
    }
    __syncthreads();
    if (b < 8) {
        float sv = 0.f;
        #pragma unroll
        for (int kk = 0; kk < 8; kk++) sv += red[b][kk];
        smu[b] = sv * (1.f / 256.f);
    }
    __syncthreads();
    float mu[8];
    #pragma unroll
    for (int d = 0; d < 8; d++) mu[d] = smu[d];
    __syncthreads();

    #pragma unroll
    for (int d = 0; d < 8; d++) {
        float dv = v[d] - mu[d];
        float sv = dv * dv;
        #pragma unroll
        for (int o = 16; o > 0; o >>= 1) sv += __shfl_xor_sync(0xffffffffu, sv, o);
        if (lane == 0) red[d][w] = sv;
    }
    __syncthreads();
    if (b < 8) {
        float sv = 0.f;
        #pragma unroll
        for (int kk = 0; kk < 8; kk++) sv += red[b][kk];
        svar[b] = sv * (1.f / 256.f);
    }
    __syncthreads();

    float acc = bfc[0];
    #pragma unroll
    for (int d = 0; d < 8; d++) {
        float bn = (v[d] - mu[d]) * rsqrtf(svar[d] + 1e-5f) * gamma[d] + beta[d];
        acc = fmaf(bn, wfc[d], acc);
    }
    out[b] = 1.f / (1.f + expf(-acc));
}

extern "C" void kernel_launch(void* const* d_in, const int* in_sizes, int n_in,
                              void* d_out, int out_size) {
    const float* X    = (const float*)d_in[0];
    const float* Wi   = (const float*)d_in[1];
    const float* Wf   = (const float*)d_in[2];
    const float* Wz   = (const float*)d_in[3];
    const float* Wo   = (const float*)d_in[4];
    const float* Ri   = (const float*)d_in[5];
    const float* Rf   = (const float*)d_in[6];
    const float* Rz   = (const float*)d_in[7];
    const float* Ro   = (const float*)d_in[8];
    const float* bi   = (const float*)d_in[9];
    const float* bf   = (const float*)d_in[10];
    const float* bz   = (const float*)d_in[11];
    const float* bo   = (const float*)d_in[12];
    const float* Wp   = (const float*)d_in[13];
    const float* bp   = (const float*)d_in[14];
    const float* gam  = (const float*)d_in[15];
    const float* bet  = (const float*)d_in[16];
    const float* Wfc  = (const float*)d_in[17];
    const float* bfc  = (const float*)d_in[18];

    cudaFuncSetAttribute(slstm_kernel,
                         cudaFuncAttributeMaxDynamicSharedMemorySize, SMEM_BYTES);
    slstm_kernel<<<128, 128, SMEM_BYTES>>>(X, Wi, Wf, Wz, Wo, Ri, Rf, Rz, Ro,
                                           bi, bf, bz, bo, Wp, bp);
    finalize_kernel<<<1, 256>>>(gam, bet, Wfc, bfc, (float*)d_out);
}

// round 17
// speedup vs baseline: 1.1517x; 1.1517x over previous
#include <cuda_runtime.h>
#include <cuda_fp16.h>

// sLSTM: B=256, T=512, D=8, H=120, L=4, NH=8, HD=15
// R7 structure with the scan matvecs in fp16x2 (HFMA2):
//  - FFMA2 (rt=3 from 64-bit RF banking) -> HFMA2 (rt=2): fma floor per step
//    drops 276 -> 184 cyc. Weight registers halve (~190 -> ~120).
//  - precision containment: cell math fp32; residual x stream kept in a
//    plain fp32 copy (projection updates fp32, regenerates the fp16 dup
//    copy); projection accumulates in fp32 (ring fp16 -> fp32 on read).
// Structure otherwise = R7: 128 CTAs x 128 thr; warp k owns head pair
// (k,k+4) for 2 batches (lanes 0-14 / 16-30), outputs packed (j, j+60),
// warp-private smem ring h-exchange, folded log2e/0.5, single-exp cell,
// 64-step chunked down-projection.

#define B_ 256
#define T_ 512
#define D_ 8
#define H_ 120
#define L_ 4
#define NPAIR 60
#define ST 61               // ring row stride (half2)
#define BST (64 * ST + 1)   // ring batch stride (half2)
#define XHS 4097            // dup-x batch stride (half2)
#define XPS 4100            // plain-x batch stride (floats)
#define LOG2E 1.4426950408889634f

typedef unsigned long long ull;

__device__ float g_last[B_ * D_];

__device__ __forceinline__ ull f2pack(float x, float y) {
    ull r; asm("mov.b64 %0, {%1, %2};" : "=l"(r) : "f"(x), "f"(y)); return r;
}
__device__ __forceinline__ void f2unpack(ull v, float& x, float& y) {
    asm("mov.b64 {%0, %1}, %2;" : "=f"(x), "=f"(y) : "l"(v));
}
__device__ __forceinline__ ull f2fma(ull a, ull b, ull c) {
    ull d; asm("fma.rn.f32x2 %0, %1, %2, %3;" : "=l"(d) : "l"(a), "l"(b), "l"(c));
    return d;
}
__device__ __forceinline__ float tanh_ap(float x) {
    float r; asm("tanh.approx.f32 %0, %1;" : "=f"(r) : "f"(x)); return r;
}
__device__ __forceinline__ float rcp_ap(float x) {
    float r; asm("rcp.approx.f32 %0, %1;" : "=f"(r) : "f"(x)); return r;
}
__device__ __forceinline__ float ex2_ap(float x) {
    float r; asm("ex2.approx.f32 %0, %1;" : "=f"(r) : "f"(x)); return r;
}

// sLSTM cell (fp32). it/ft pre-scaled by log2e, ot pre-scaled by 0.5.
__device__ __forceinline__ float cellf(float it, float ft, float zt, float ot,
                                       float& c, float& nn, float& m) {
    float z  = tanh_ap(zt);
    float o  = fmaf(tanh_ap(ot), 0.5f, 0.5f);
    float b  = ft + m;
    float mn = fmaxf(it, b);
    float e  = ex2_ap(-fabsf(it - b));
    bool ag  = (it >= b);
    float ip = ag ? 1.f : e;
    float fp = ag ? e : 1.f;
    c  = fp * c  + ip * z;
    nn = fp * nn + ip;
    m  = mn;
    return o * c * rcp_ap(nn);
}

// shared layout (bytes):
//   wp2 [8*60] ull (paired fp32 Wp)        @0      3840
//   xh  [2][XHS] half2 (dup x)             @3840   32776
//   hsb [2][BST] half2 (h ring)            @36616  31240
//   xp  [2][XPS] float (plain x stream)    @67856  32800
//   bps [8] float                          @100656 32
#define OFF_WP 0
#define OFF_XH 3840
#define OFF_HS (OFF_XH + 2 * XHS * 4)
#define OFF_XP (OFF_HS + 2 * BST * 4)
#define OFF_BP (OFF_XP + 2 * XPS * 4)
#define SMEM_BYTES (OFF_BP + 64)

__global__ void __launch_bounds__(128, 1) slstm_kernel(
    const float* __restrict__ X,
    const float* __restrict__ Wi, const float* __restrict__ Wf,
    const float* __restrict__ Wz, const float* __restrict__ Wo,
    const float* __restrict__ Ri, const float* __restrict__ Rf,
    const float* __restrict__ Rz, const float* __restrict__ Ro,
    const float* __restrict__ bi, const float* __restrict__ bf,
    const float* __restrict__ bz, const float* __restrict__ bo,
    const float* __restrict__ Wp, const float* __restrict__ bp)
{
    extern __shared__ char smemraw[];
    ull*     wp2 = (ull*)(smemraw + OFF_WP);
    __half2* xh  = (__half2*)(smemraw + OFF_XH);
    __half2* hsb = (__half2*)(smemraw + OFF_HS);
    float*   xp  = (float*)(smemraw + OFF_XP);
    float*   bps = (float*)(smemraw + OFF_BP);

    const int tid  = threadIdx.x;
    const int lane = tid & 31;
    const int k    = tid >> 5;           // warp id == head block (pairs k+4)
    const int half = (lane >> 4) & 1;    // batch within CTA
    const int e    = lane & 15;
    const bool act = (e < 15);
    const int b0   = blockIdx.x * 2;
    const int ec   = act ? e : 14;
    const int slot = k * 15 + ec;

    // load input x: plain fp32 + duplicated fp16x2
    for (int idx = tid; idx < 2 * T_ * D_; idx += 128) {
        int bbi = idx >> 12;
        int i   = idx & 4095;
        float v = X[(b0 + bbi) * (T_ * D_) + i];
        xp[bbi * XPS + i] = v;
        xh[bbi * XHS + i] = __float2half2_rn(v);
    }

    #pragma unroll 1
    for (int l = 0; l < L_; l++) {
        // ---- packed fp16x2 weights (i/f scaled log2e, o scaled .5) ----
        __half2 rIv[15], rFv[15], rZv[15], rOv[15];
        __half2 wIv[8],  wFv[8],  wZv[8],  wOv[8];
        __half2 bIv, bFv, bZv, bOv;
        {
            const int j0 = slot, j1 = slot + 60;
            const float* wi = Wi + l * H_ * D_;
            const float* wf = Wf + l * H_ * D_;
            const float* wz = Wz + l * H_ * D_;
            const float* wo = Wo + l * H_ * D_;
            #pragma unroll
            for (int d = 0; d < 8; d++) {
                wIv[d] = __floats2half2_rn(LOG2E * wi[j0 * 8 + d], LOG2E * wi[j1 * 8 + d]);
                wFv[d] = __floats2half2_rn(LOG2E * wf[j0 * 8 + d], LOG2E * wf[j1 * 8 + d]);
                wZv[d] = __floats2half2_rn(wz[j0 * 8 + d], wz[j1 * 8 + d]);
                wOv[d] = __floats2half2_rn(0.5f * wo[j0 * 8 + d], 0.5f * wo[j1 * 8 + d]);
            }
            const float* ri = Ri + l * 8 * 225;
            const float* rf = Rf + l * 8 * 225;
            const float* rz = Rz + l * 8 * 225;
            const float* ro = Ro + l * 8 * 225;
            #pragma unroll
            for (int d = 0; d < 15; d++) {
                int i0 = k * 225 + d * 15 + ec;
                int i1 = (k + 4) * 225 + d * 15 + ec;
                rIv[d] = __floats2half2_rn(LOG2E * ri[i0], LOG2E * ri[i1]);
                rFv[d] = __floats2half2_rn(LOG2E * rf[i0], LOG2E * rf[i1]);
                rZv[d] = __floats2half2_rn(rz[i0], rz[i1]);
                rOv[d] = __floats2half2_rn(0.5f * ro[i0], 0.5f * ro[i1]);
            }
            bIv = __floats2half2_rn(LOG2E * bi[l * H_ + j0], LOG2E * bi[l * H_ + j1]);
            bFv = __floats2half2_rn(LOG2E * bf[l * H_ + j0], LOG2E * bf[l * H_ + j1]);
            bZv = __floats2half2_rn(bz[l * H_ + j0], bz[l * H_ + j1]);
            bOv = __floats2half2_rn(0.5f * bo[l * H_ + j0], 0.5f * bo[l * H_ + j1]);
        }
        // paired fp32 Wp + bp
        for (int idx = tid; idx < 8 * NPAIR; idx += 128) {
            int d = idx / NPAIR, p = idx - d * NPAIR;
            const float* wp = Wp + l * D_ * H_;
            wp2[idx] = f2pack(wp[d * H_ + p], wp[d * H_ + p + 60]);
        }
        if (tid < 8) bps[tid] = bp[l * D_ + tid];
        // zero the ring's "step -1" row
        if (act) {
            hsb[0 * BST + 63 * ST + slot] = __float2half2_rn(0.f);
            hsb[1 * BST + 63 * ST + slot] = __float2half2_rn(0.f);
        }
        __syncthreads();

        float c0 = 0.f, c1 = 0.f, n0 = 0.f, n1 = 0.f, m0 = 0.f, m1 = 0.f;

        __half2* __restrict__ hrow = hsb + half * BST;
        const int hoff = k * 15;

        #pragma unroll 1
        for (int ch = 0; ch < 8; ch++) {
            const int tbase = ch * 64;
            // ---- scan 64 steps: warp-private ring, HFMA2 matvecs ----
            #pragma unroll 2
            for (int tt = 0; tt < 64; tt++) {
                const int p = (tt - 1) & 63;
                __half2 aI = bIv, aF = bFv, aZ = bZv, aO = bOv;
                const __half2* __restrict__ xr = xh + half * XHS + (tbase + tt) * 8;
                #pragma unroll
                for (int d = 0; d < 8; d++) {
                    __half2 xv = xr[d];
                    aI = __hfma2(xv, wIv[d], aI);
                    aF = __hfma2(xv, wFv[d], aF);
                    aZ = __hfma2(xv, wZv[d], aZ);
                    aO = __hfma2(xv, wOv[d], aO);
                }
                const __half2* __restrict__ hr = hrow + p * ST + hoff;
                #pragma unroll
                for (int d = 0; d < 15; d++) {
                    __half2 hv = hr[d];
                    aI = __hfma2(hv, rIv[d], aI);
                    aF = __hfma2(hv, rFv[d], aF);
                    aZ = __hfma2(hv, rZv[d], aZ);
                    aO = __hfma2(hv, rOv[d], aO);
                }
                float itx = __low2float(aI), ity = __high2float(aI);
                float ftx = __low2float(aF), fty = __high2float(aF);
                float ztx = __low2float(aZ), zty = __high2float(aZ);
                float otx = __low2float(aO), oty = __high2float(aO);
                float h0 = cellf(itx, ftx, ztx, otx, c0, n0, m0);
                float h1 = cellf(ity, fty, zty, oty, c1, n1, m1);
                if (act)
                    hrow[tt * ST + slot] = __floats2half2_rn(h0, h1);
            }
            __syncthreads();
            // ---- projection (fp32 accum): x[t] += hs[t] @ Wp^T + bp ----
            {
                const int tl = tid & 63;
                const int bb = tid >> 6;
                ull acc[8];
                #pragma unroll
                for (int d = 0; d < 8; d++) acc[d] = 0ull;
                const __half2* __restrict__ hsr = hsb + bb * BST + tl * ST;
                #pragma unroll 4
                for (int pp = 0; pp < NPAIR; pp++) {
                    __half2 hq = hsr[pp];
                    ull hvv = f2pack(__low2float(hq), __high2float(hq));
                    #pragma unroll
                    for (int d = 0; d < 8; d++)
                        acc[d] = f2fma(hvv, wp2[d * NPAIR + pp], acc[d]);
                }
                float*   xw  = xp + bb * XPS + (tbase + tl) * 8;
                __half2* xwh = xh + bb * XHS + (tbase + tl) * 8;
                #pragma unroll
                for (int d = 0; d < 8; d++) {
                    float ax, ay; f2unpack(acc[d], ax, ay);
                    float nv = xw[d] + ax + ay + bps[d];
                    xw[d]  = nv;
                    xwh[d] = __float2half2_rn(nv);
                }
            }
            __syncthreads();
        }
    }

    if (tid < 16) {
        int bbi = tid >> 3, d = tid & 7;
        g_last[(b0 + bbi) * D_ + d] = xp[bbi * XPS + 511 * 8 + d];
    }
}

__global__ void finalize_kernel(const float* __restrict__ gamma,
                                const float* __restrict__ beta,
                                const float* __restrict__ wfc,
                                const float* __restrict__ bfc,
                                float* __restrict__ out)
{
    __shared__ float red[8][8];
    __shared__ float smu[8], svar[8];
    int b = threadIdx.x;
    int lane = b & 31, w = b >> 5;
    float v[8];
    #pragma unroll
    for (int d = 0; d < 8; d++) v[d] = g_last[b * 8 + d];

    #pragma unroll
    for (int d = 0; d < 8; d++) {
        float sv = v[d];
        #pragma unroll
        for (int o = 16; o > 0; o >>= 1) sv += __shfl_xor_sync(0xffffffffu, sv, o);
        if (lane == 0) red[d][w] = sv;
    }
    __syncthreads();
    if (b < 8) {
        float sv = 0.f;
        #pragma unroll
        for (int kk = 0; kk < 8; kk++) sv += red[b][kk];
        smu[b] = sv * (1.f / 256.f);
    }
    __syncthreads();
    float mu[8];
    #pragma unroll
    for (int d = 0; d < 8; d++) mu[d] = smu[d];
    __syncthreads();

    #pragma unroll
    for (int d = 0; d < 8; d++) {
        float dv = v[d] - mu[d];
        float sv = dv * dv;
        #pragma unroll
        for (int o = 16; o > 0; o >>= 1) sv += __shfl_xor_sync(0xffffffffu, sv, o);
        if (lane == 0) red[d][w] = sv;
    }
    __syncthreads();
    if (b < 8) {
        float sv = 0.f;
        #pragma unroll
        for (int kk = 0; kk < 8; kk++) sv += red[b][kk];
        svar[b] = sv * (1.f / 256.f);
    }
    __syncthreads();

    float acc = bfc[0];
    #pragma unroll
    for (int d = 0; d < 8; d++) {
        float bn = (v[d] - mu[d]) * rsqrtf(svar[d] + 1e-5f) * gamma[d] + beta[d];
        acc = fmaf(bn, wfc[d], acc);
    }
    out[b] = 1.f / (1.f + expf(-acc));
}

extern "C" void kernel_launch(void* const* d_in, const int* in_sizes, int n_in,
                              void* d_out, int out_size) {
    const float* X    = (const float*)d_in[0];
    const float* Wi   = (const float*)d_in[1];
    const float* Wf   = (const float*)d_in[2];
    const float* Wz   = (const float*)d_in[3];
    const float* Wo   = (const float*)d_in[4];
    const float* Ri   = (const float*)d_in[5];
    const float* Rf   = (const float*)d_in[6];
    const float* Rz   = (const float*)d_in[7];
    const float* Ro   = (const float*)d_in[8];
    const float* bi   = (const float*)d_in[9];
    const float* bf   = (const float*)d_in[10];
    const float* bz   = (const float*)d_in[11];
    const float* bo   = (const float*)d_in[12];
    const float* Wp   = (const float*)d_in[13];
    const float* bp   = (const float*)d_in[14];
    const float* gam  = (const float*)d_in[15];
    const float* bet  = (const float*)d_in[16];
    const float* Wfc  = (const float*)d_in[17];
    const float* bfc  = (const float*)d_in[18];

    cudaFuncSetAttribute(slstm_kernel,
                         cudaFuncAttributeMaxDynamicSharedMemorySize, SMEM_BYTES);
    slstm_kernel<<<128, 128, SMEM_BYTES>>>(X, Wi, Wf, Wz, Wo, Ri, Rf, Rz, Ro,
                                           bi, bf, bz, bo, Wp, bp);
    finalize_kernel<<<1, 256>>>(gam, bet, Wfc, bfc, (float*)d_out);
}